// round 1
// baseline (speedup 1.0000x reference)
#include <cuda_runtime.h>
#include <cuda_bf16.h>
#include <math.h>
#include <stdint.h>

#define NN 50000
#define NE 800000
#define HDIM 64

// ---------------- scratch (static device globals; no allocation) ----------------
__device__ int   g_src[NE];
__device__ int   g_dst[NE];
__device__ int   g_deg[NN];
__device__ int   g_rowstart[NN + 1];
__device__ int   g_cursor[NN];
__device__ int   g_elist[NE];
__device__ float g_xl[NN * HDIM];
__device__ float g_xr[NN * HDIM];
__device__ float g_res[NN * HDIM];
__device__ float g_score[NE * 4];
__device__ float g_m[NN * 4];
__device__ float g_denom[NN * 4];

// ---------------- K0: edge index convert (+int64 detect) + zero deg ----------------
__global__ void k_convert(const int* __restrict__ ei) {
    __shared__ int s64;
    if (threadIdx.x == 0) {
        int f = 1;
#pragma unroll
        for (int i = 0; i < 16; i++) f &= (ei[2 * i + 1] == 0);
        s64 = f;
    }
    __syncthreads();
    int is64 = s64;
    int e = blockIdx.x * blockDim.x + threadIdx.x;
    if (e < NE) {
        if (is64) {
            g_src[e] = ei[2 * e];
            g_dst[e] = ei[2 * (NE + e)];
        } else {
            g_src[e] = ei[e];
            g_dst[e] = ei[NE + e];
        }
    }
    if (e < NN) g_deg[e] = 0;
}

// ---------------- K1: fused projections x@Wl+bl, x@Wr+br, x@Wres+bres ----------------
// Block: 192 threads (warps 0-1 -> Wl, 2-3 -> Wr, 4-5 -> Wres), 32 rows per block.
// x tile stored transposed in smem so row pairs are contiguous for fma.rn.f32x2.
__global__ void __launch_bounds__(192) k_proj(
    const float* __restrict__ x,
    const float* __restrict__ Wl, const float* __restrict__ bl,
    const float* __restrict__ Wr, const float* __restrict__ br,
    const float* __restrict__ Wres, const float* __restrict__ bres)
{
    __shared__ __align__(16) float sx[128 * 34];  // [k][r], stride 34 (even, conflict-mitigating)
    int tid = threadIdx.x;
    int row0 = blockIdx.x * 32;
    const float4* x4 = reinterpret_cast<const float4*>(x);
    for (int idx = tid; idx < 1024; idx += 192) {
        int r = idx & 31, c4 = idx >> 5;
        int row = row0 + r;
        float4 v = make_float4(0.f, 0.f, 0.f, 0.f);
        if (row < NN) v = x4[row * 32 + c4];
        int k = c4 * 4;
        sx[(k + 0) * 34 + r] = v.x;
        sx[(k + 1) * 34 + r] = v.y;
        sx[(k + 2) * 34 + r] = v.z;
        sx[(k + 3) * 34 + r] = v.w;
    }
    __syncthreads();

    int sel = tid / 64;       // which matrix
    int jj  = tid & 63;       // output column
    const float* W = (sel == 0) ? Wl : (sel == 1) ? Wr : Wres;
    const float* B = (sel == 0) ? bl : (sel == 1) ? br : bres;
    float* Out = (sel == 0) ? g_xl : (sel == 1) ? g_xr : g_res;

    unsigned long long acc[16];
#pragma unroll
    for (int i = 0; i < 16; i++) acc[i] = 0ULL;   // (0.f, 0.f)

#pragma unroll 4
    for (int k = 0; k < 128; k++) {
        float w = W[k * 64 + jj];
        unsigned long long wd;
        asm("mov.b64 %0, {%1, %2};" : "=l"(wd) : "f"(w), "f"(w));
        const unsigned long long* xp =
            reinterpret_cast<const unsigned long long*>(&sx[k * 34]);
#pragma unroll
        for (int rp = 0; rp < 16; rp++) {
            unsigned long long xv = xp[rp];
            asm("fma.rn.f32x2 %0, %1, %2, %0;" : "+l"(acc[rp]) : "l"(xv), "l"(wd));
        }
    }

    float b = B[jj];
#pragma unroll
    for (int rp = 0; rp < 16; rp++) {
        int row = row0 + 2 * rp;
        float lo = __uint_as_float((unsigned)(acc[rp] & 0xffffffffULL)) + b;
        float hi = __uint_as_float((unsigned)(acc[rp] >> 32)) + b;
        if (row < NN)     Out[row * 64 + jj] = lo;
        if (row + 1 < NN) Out[(row + 1) * 64 + jj] = hi;
    }
}

// ---------------- K2: degree histogram ----------------
__global__ void k_hist() {
    int e = blockIdx.x * blockDim.x + threadIdx.x;
    if (e < NE) atomicAdd(&g_deg[g_dst[e]], 1);
}

// ---------------- K3: exclusive scan (single block) ----------------
__global__ void k_scan() {
    const int T = 1024, CH = 49;  // 1024*49 = 50176 >= 50001
    __shared__ int sm[T];
    int t = threadIdx.x;
    int base = t * CH;
    int s = 0;
    for (int i = 0; i < CH; i++) {
        int idx = base + i;
        if (idx < NN) s += g_deg[idx];
    }
    sm[t] = s;
    __syncthreads();
    for (int off = 1; off < T; off <<= 1) {
        int v = (t >= off) ? sm[t - off] : 0;
        __syncthreads();
        sm[t] += v;
        __syncthreads();
    }
    int run = sm[t] - s;  // exclusive prefix of this thread's chunk
    for (int i = 0; i < CH; i++) {
        int idx = base + i;
        if (idx < NN) {
            g_rowstart[idx] = run;
            g_cursor[idx]   = run;
            run += g_deg[idx];
        } else if (idx == NN) {
            g_rowstart[NN] = run;
        }
    }
}

// ---------------- K4: scatter edges into CSR ----------------
__global__ void k_scatter() {
    int e = blockIdx.x * blockDim.x + threadIdx.x;
    if (e < NE) {
        int d = g_dst[e];
        int pos = atomicAdd(&g_cursor[d], 1);
        g_elist[pos] = e;
    }
}

// ---------------- K5: per-node fused score + online softmax + aggregation + epilogue ----------------
// One warp per node. lane l owns output elements (2l, 2l+1); head = l>>3.
__global__ void __launch_bounds__(256) k_node(
    const float* __restrict__ edge_attr,
    const float* __restrict__ We,
    const float* __restrict__ att,
    const float* __restrict__ bias_out,
    float* __restrict__ out)
{
    __shared__ int sbuf[8 * 128];
    int warp = threadIdx.x >> 5;
    int lane = threadIdx.x & 31;
    int n = blockIdx.x * 8 + warp;
    if (n >= NN) return;
    int* buf = &sbuf[warp * 128];

    int start = g_rowstart[n];
    int deg = g_rowstart[n + 1] - start;

    // deterministic: sort this node's edge ids ascending
    if (deg <= 32) {
        int myid = (lane < deg) ? g_elist[start + lane] : 0x7fffffff;
        int rank = 0;
#pragma unroll
        for (int j = 0; j < 32; j++) {
            int o = __shfl_sync(0xffffffffu, myid, j);
            rank += (o < myid);
        }
        if (lane < deg) buf[rank] = myid;
    } else {
        int dd = min(deg, 128);
        for (int i = lane; i < dd; i += 32) {
            int v = g_elist[start + i];
            int rank = 0;
            for (int j = 0; j < dd; j++) rank += (g_elist[start + j] < v);
            buf[rank] = v;
        }
    }
    __syncwarp();
    bool use_buf = (deg <= 128);

    float2 xr2 = *(const float2*)&g_xr[n * 64 + 2 * lane];
    float2 We2 = *(const float2*)&We[2 * lane];
    float2 at2 = *(const float2*)&att[2 * lane];

    float m = __int_as_float(0xff800000);  // -inf
    float denom = 0.f;
    float accx = 0.f, accy = 0.f;

    int e = 0, src = 0; float ea = 0.f;
    if (deg > 0) {
        e = use_buf ? buf[0] : g_elist[start];
        src = g_src[e];
        ea = edge_attr[e];
    }
    for (int i = 0; i < deg; i++) {
        float2 xl2 = *(const float2*)&g_xl[src * 64 + 2 * lane];
        int ecur = e;
        float eacur = ea;
        if (i + 1 < deg) {   // prefetch next edge meta
            e = use_buf ? buf[i + 1] : g_elist[start + i + 1];
            src = g_src[e];
            ea = edge_attr[e];
        }
        float fx = xl2.x + xr2.x + eacur * We2.x;
        float fy = xl2.y + xr2.y + eacur * We2.y;
        fx = fx >= 0.f ? fx : 0.2f * fx;
        fy = fy >= 0.f ? fy : 0.2f * fy;
        float p = fx * at2.x + fy * at2.y;
        p += __shfl_xor_sync(0xffffffffu, p, 1);
        p += __shfl_xor_sync(0xffffffffu, p, 2);
        p += __shfl_xor_sync(0xffffffffu, p, 4);
        // p is now this head's score for edge ecur
        if ((lane & 7) == 0) g_score[ecur * 4 + (lane >> 3)] = p;
        float mnew = fmaxf(m, p);
        float scale = __expf(m - mnew);   // m=-inf -> 0
        float ex = __expf(p - mnew);
        denom = denom * scale + ex;
        accx = accx * scale + ex * xl2.x;
        accy = accy * scale + ex * xl2.y;
        m = mnew;
    }

    float dfin = denom + 1e-16f;
    float2 r2  = *(const float2*)&g_res[n * 64 + 2 * lane];
    float2 bo2 = *(const float2*)&bias_out[2 * lane];
    float ox = accx / dfin + bo2.x + r2.x;
    float oy = accy / dfin + bo2.y + r2.y;
    ox = ox > 0.f ? ox : expm1f(ox);
    oy = oy > 0.f ? oy : expm1f(oy);
    *(float2*)&out[n * 64 + 2 * lane] = make_float2(ox, oy);
    if ((lane & 7) == 0) {
        g_m[n * 4 + (lane >> 3)] = m;
        g_denom[n * 4 + (lane >> 3)] = denom;
    }
}

// ---------------- K6: edge_index passthrough as float ----------------
__global__ void k_ei(float* __restrict__ out) {
    int e = blockIdx.x * blockDim.x + threadIdx.x;
    if (e < NE) {
        const long long OFF = 3200000LL;
        out[OFF + e]      = (float)g_src[e];
        out[OFF + NE + e] = (float)g_dst[e];
    }
}

// ---------------- K7: alpha = exp(score - m[dst]) / (denom[dst] + 1e-16) ----------------
__global__ void k_alpha(float* __restrict__ out) {
    int e = blockIdx.x * blockDim.x + threadIdx.x;
    if (e >= NE) return;
    float4 s4 = *(const float4*)&g_score[e * 4];
    int d = g_dst[e];
    float4 m4  = *(const float4*)&g_m[d * 4];
    float4 dn4 = *(const float4*)&g_denom[d * 4];
    float4 a;
    a.x = __expf(s4.x - m4.x) / (dn4.x + 1e-16f);
    a.y = __expf(s4.y - m4.y) / (dn4.y + 1e-16f);
    a.z = __expf(s4.z - m4.z) / (dn4.z + 1e-16f);
    a.w = __expf(s4.w - m4.w) / (dn4.w + 1e-16f);
    const long long OFF = 4800000LL;
    *(float4*)&out[OFF + e * 4] = a;
}

// ---------------- launch ----------------
extern "C" void kernel_launch(void* const* d_in, const int* in_sizes, int n_in,
                              void* d_out, int out_size) {
    const float* x         = (const float*)d_in[0];
    const int*   ei        = (const int*)d_in[1];
    const float* edge_attr = (const float*)d_in[2];
    const float* Wl        = (const float*)d_in[3];
    const float* bl        = (const float*)d_in[4];
    const float* Wr        = (const float*)d_in[5];
    const float* br        = (const float*)d_in[6];
    const float* We        = (const float*)d_in[7];
    const float* att       = (const float*)d_in[8];
    const float* bias_out  = (const float*)d_in[9];
    const float* Wres      = (const float*)d_in[10];
    const float* bres      = (const float*)d_in[11];
    float* out = (float*)d_out;

    k_convert<<<(NE + 255) / 256, 256>>>(ei);
    k_proj<<<(NN + 31) / 32, 192>>>(x, Wl, bl, Wr, br, Wres, bres);
    k_hist<<<(NE + 255) / 256, 256>>>();
    k_scan<<<1, 1024>>>();
    k_scatter<<<(NE + 255) / 256, 256>>>();
    k_node<<<(NN + 7) / 8, 256>>>(edge_attr, We, att, bias_out, out);

    if (out_size >= 4800000) k_ei<<<(NE + 255) / 256, 256>>>(out);
    if (out_size >= 8000000) k_alpha<<<(NE + 255) / 256, 256>>>(out);
}

// round 2
// speedup vs baseline: 2.1194x; 2.1194x over previous
#include <cuda_runtime.h>
#include <cuda_bf16.h>
#include <math.h>
#include <stdint.h>

#define NN 50000
#define NE 800000
#define HDIM 64
#define NBLK 196   // ceil(50000/256)

// ---------------- scratch (static device globals; no allocation) ----------------
__device__ int   g_src[NE];
__device__ int   g_dst[NE];
__device__ int   g_deg[NN];
__device__ int   g_rowstart[NN + 1];
__device__ int   g_cursor[NN];
__device__ int   g_elist[NE];
__device__ int   g_part[256];
__device__ float g_xl[NN * HDIM];
__device__ float g_xr[NN * HDIM];
__device__ float g_res[NN * HDIM];
__device__ float g_score[NE * 4];
__device__ float g_m[NN * 4];
__device__ float g_denom[NN * 4];

// ---------------- K0: edge index convert (+int64 detect) + zero deg ----------------
__global__ void k_convert(const int* __restrict__ ei) {
    __shared__ int s64;
    if (threadIdx.x == 0) {
        int f = 1;
#pragma unroll
        for (int i = 0; i < 16; i++) f &= (ei[2 * i + 1] == 0);
        s64 = f;
    }
    __syncthreads();
    int is64 = s64;
    int e = blockIdx.x * blockDim.x + threadIdx.x;
    if (e < NE) {
        if (is64) {
            g_src[e] = ei[2 * e];
            g_dst[e] = ei[2 * (NE + e)];
        } else {
            g_src[e] = ei[e];
            g_dst[e] = ei[NE + e];
        }
    }
    if (e < NN) g_deg[e] = 0;
}

// ---------------- K1: fused projections, register-blocked ----------------
// Block: 192 threads = 6 warps; warp w: matrix = w%3, row-half = w/3 (16 rows).
// lane owns cols (lane, lane+32); 8 f32x2 row-pair accumulators per col.
// x tile transposed in smem; x reads are lane-uniform broadcasts (1 wavefront).
__global__ void __launch_bounds__(192) k_proj(
    const float* __restrict__ x,
    const float* __restrict__ Wl, const float* __restrict__ bl,
    const float* __restrict__ Wr, const float* __restrict__ br,
    const float* __restrict__ Wres, const float* __restrict__ bres)
{
    __shared__ __align__(16) float sx[128 * 32];  // [k][r]
    int tid = threadIdx.x;
    int lane = tid & 31;
    int warp = tid >> 5;
    int row0 = blockIdx.x * 32;
    const float4* x4 = reinterpret_cast<const float4*>(x);
    for (int idx = tid; idx < 1024; idx += 192) {
        int r = idx & 31, c4 = idx >> 5;
        int row = row0 + r;
        float4 v = make_float4(0.f, 0.f, 0.f, 0.f);
        if (row < NN) v = x4[row * 32 + c4];
        int k = c4 * 4;
        sx[(k + 0) * 32 + r] = v.x;
        sx[(k + 1) * 32 + r] = v.y;
        sx[(k + 2) * 32 + r] = v.z;
        sx[(k + 3) * 32 + r] = v.w;
    }
    __syncthreads();

    int mat = warp % 3;
    int rh  = warp / 3;    // 0 or 1 -> rows [rh*16, rh*16+16)
    const float* W = (mat == 0) ? Wl : (mat == 1) ? Wr : Wres;
    const float* B = (mat == 0) ? bl : (mat == 1) ? br : bres;
    float* Out = (mat == 0) ? g_xl : (mat == 1) ? g_xr : g_res;
    int j0 = lane, j1 = lane + 32;

    unsigned long long acc0[8], acc1[8];
#pragma unroll
    for (int i = 0; i < 8; i++) { acc0[i] = 0ULL; acc1[i] = 0ULL; }

#pragma unroll 2
    for (int k = 0; k < 128; k++) {
        float w0 = W[k * 64 + j0];
        float w1 = W[k * 64 + j1];
        unsigned long long wd0, wd1;
        asm("mov.b64 %0, {%1, %2};" : "=l"(wd0) : "f"(w0), "f"(w0));
        asm("mov.b64 %0, {%1, %2};" : "=l"(wd1) : "f"(w1), "f"(w1));
        const unsigned long long* xp =
            reinterpret_cast<const unsigned long long*>(&sx[k * 32 + rh * 16]);
#pragma unroll
        for (int rp = 0; rp < 8; rp++) {
            unsigned long long xv = xp[rp];   // lane-uniform -> broadcast
            asm("fma.rn.f32x2 %0, %1, %2, %0;" : "+l"(acc0[rp]) : "l"(xv), "l"(wd0));
            asm("fma.rn.f32x2 %0, %1, %2, %0;" : "+l"(acc1[rp]) : "l"(xv), "l"(wd1));
        }
    }

    float b0 = B[j0], b1 = B[j1];
#pragma unroll
    for (int rp = 0; rp < 8; rp++) {
        int row = row0 + rh * 16 + 2 * rp;
        float lo0 = __uint_as_float((unsigned)(acc0[rp] & 0xffffffffULL)) + b0;
        float hi0 = __uint_as_float((unsigned)(acc0[rp] >> 32)) + b0;
        float lo1 = __uint_as_float((unsigned)(acc1[rp] & 0xffffffffULL)) + b1;
        float hi1 = __uint_as_float((unsigned)(acc1[rp] >> 32)) + b1;
        if (row < NN)     { Out[row * 64 + j0] = lo0; Out[row * 64 + j1] = lo1; }
        if (row + 1 < NN) { Out[(row + 1) * 64 + j0] = hi0; Out[(row + 1) * 64 + j1] = hi1; }
    }
}

// ---------------- K2: degree histogram ----------------
__global__ void k_hist() {
    int e = blockIdx.x * blockDim.x + threadIdx.x;
    if (e < NE) atomicAdd(&g_deg[g_dst[e]], 1);
}

// ---------------- K3a: per-block partial sums ----------------
__global__ void k_scan1() {
    __shared__ int s[256];
    int t = threadIdx.x;
    int idx = blockIdx.x * 256 + t;
    int v = (idx < NN) ? g_deg[idx] : 0;
    s[t] = v;
    __syncthreads();
#pragma unroll
    for (int off = 128; off > 0; off >>= 1) {
        if (t < off) s[t] += s[t + off];
        __syncthreads();
    }
    if (t == 0) g_part[blockIdx.x] = s[0];
}

// ---------------- K3b: scan of partials (1 block) ----------------
__global__ void k_scan2() {
    __shared__ int s[256];
    int t = threadIdx.x;
    int v = (t < NBLK) ? g_part[t] : 0;
    s[t] = v;
    __syncthreads();
#pragma unroll
    for (int off = 1; off < 256; off <<= 1) {
        int u = (t >= off) ? s[t - off] : 0;
        __syncthreads();
        s[t] += u;
        __syncthreads();
    }
    if (t < NBLK) g_part[t] = s[t] - v;   // exclusive block offset
    if (t == 255) g_rowstart[NN] = s[255];
}

// ---------------- K3c: local exclusive scan + block offset ----------------
__global__ void k_scan3() {
    __shared__ int s[256];
    int t = threadIdx.x;
    int idx = blockIdx.x * 256 + t;
    int v = (idx < NN) ? g_deg[idx] : 0;
    s[t] = v;
    __syncthreads();
#pragma unroll
    for (int off = 1; off < 256; off <<= 1) {
        int u = (t >= off) ? s[t - off] : 0;
        __syncthreads();
        s[t] += u;
        __syncthreads();
    }
    int excl = s[t] - v + g_part[blockIdx.x];
    if (idx < NN) {
        g_rowstart[idx] = excl;
        g_cursor[idx]   = excl;
    }
}

// ---------------- K4: scatter edges into CSR ----------------
__global__ void k_scatter() {
    int e = blockIdx.x * blockDim.x + threadIdx.x;
    if (e < NE) {
        int d = g_dst[e];
        int pos = atomicAdd(&g_cursor[d], 1);
        g_elist[pos] = e;
    }
}

// ---------------- K5: per-node fused score + online softmax + aggregation + epilogue ----------------
__global__ void __launch_bounds__(256) k_node(
    const float* __restrict__ edge_attr,
    const float* __restrict__ We,
    const float* __restrict__ att,
    const float* __restrict__ bias_out,
    float* __restrict__ out)
{
    __shared__ int sbuf[8 * 128];
    int warp = threadIdx.x >> 5;
    int lane = threadIdx.x & 31;
    int n = blockIdx.x * 8 + warp;
    if (n >= NN) return;
    int* buf = &sbuf[warp * 128];

    int start = g_rowstart[n];
    int deg = g_rowstart[n + 1] - start;

    // deterministic: sort this node's edge ids ascending
    if (deg <= 32) {
        int myid = (lane < deg) ? g_elist[start + lane] : 0x7fffffff;
        int rank = 0;
#pragma unroll
        for (int j = 0; j < 32; j++) {
            int o = __shfl_sync(0xffffffffu, myid, j);
            rank += (o < myid);
        }
        if (lane < deg) buf[rank] = myid;
    } else {
        int dd = min(deg, 128);
        for (int i = lane; i < dd; i += 32) {
            int v = g_elist[start + i];
            int rank = 0;
            for (int j = 0; j < dd; j++) rank += (g_elist[start + j] < v);
            buf[rank] = v;
        }
    }
    __syncwarp();
    bool use_buf = (deg <= 128);

    float2 xr2 = *(const float2*)&g_xr[n * 64 + 2 * lane];
    float2 We2 = *(const float2*)&We[2 * lane];
    float2 at2 = *(const float2*)&att[2 * lane];

    float m = __int_as_float(0xff800000);  // -inf
    float denom = 0.f;
    float accx = 0.f, accy = 0.f;

    int e = 0, src = 0; float ea = 0.f;
    if (deg > 0) {
        e = use_buf ? buf[0] : g_elist[start];
        src = g_src[e];
        ea = edge_attr[e];
    }
    for (int i = 0; i < deg; i++) {
        float2 xl2 = *(const float2*)&g_xl[src * 64 + 2 * lane];
        int ecur = e;
        float eacur = ea;
        if (i + 1 < deg) {   // prefetch next edge meta
            e = use_buf ? buf[i + 1] : g_elist[start + i + 1];
            src = g_src[e];
            ea = edge_attr[e];
        }
        float fx = xl2.x + xr2.x + eacur * We2.x;
        float fy = xl2.y + xr2.y + eacur * We2.y;
        fx = fx >= 0.f ? fx : 0.2f * fx;
        fy = fy >= 0.f ? fy : 0.2f * fy;
        float p = fx * at2.x + fy * at2.y;
        p += __shfl_xor_sync(0xffffffffu, p, 1);
        p += __shfl_xor_sync(0xffffffffu, p, 2);
        p += __shfl_xor_sync(0xffffffffu, p, 4);
        if ((lane & 7) == 0) g_score[ecur * 4 + (lane >> 3)] = p;
        float mnew = fmaxf(m, p);
        float scale = __expf(m - mnew);
        float ex = __expf(p - mnew);
        denom = denom * scale + ex;
        accx = accx * scale + ex * xl2.x;
        accy = accy * scale + ex * xl2.y;
        m = mnew;
    }

    float dfin = denom + 1e-16f;
    float2 r2  = *(const float2*)&g_res[n * 64 + 2 * lane];
    float2 bo2 = *(const float2*)&bias_out[2 * lane];
    float ox = accx / dfin + bo2.x + r2.x;
    float oy = accy / dfin + bo2.y + r2.y;
    ox = ox > 0.f ? ox : expm1f(ox);
    oy = oy > 0.f ? oy : expm1f(oy);
    *(float2*)&out[n * 64 + 2 * lane] = make_float2(ox, oy);
    if ((lane & 7) == 0) {
        g_m[n * 4 + (lane >> 3)] = m;
        g_denom[n * 4 + (lane >> 3)] = denom;
    }
}

// ---------------- K6: edge_index passthrough as float ----------------
__global__ void k_ei(float* __restrict__ out) {
    int e = blockIdx.x * blockDim.x + threadIdx.x;
    if (e < NE) {
        const long long OFF = 3200000LL;
        out[OFF + e]      = (float)g_src[e];
        out[OFF + NE + e] = (float)g_dst[e];
    }
}

// ---------------- K7: alpha ----------------
__global__ void k_alpha(float* __restrict__ out) {
    int e = blockIdx.x * blockDim.x + threadIdx.x;
    if (e >= NE) return;
    float4 s4 = *(const float4*)&g_score[e * 4];
    int d = g_dst[e];
    float4 m4  = *(const float4*)&g_m[d * 4];
    float4 dn4 = *(const float4*)&g_denom[d * 4];
    float4 a;
    a.x = __expf(s4.x - m4.x) / (dn4.x + 1e-16f);
    a.y = __expf(s4.y - m4.y) / (dn4.y + 1e-16f);
    a.z = __expf(s4.z - m4.z) / (dn4.z + 1e-16f);
    a.w = __expf(s4.w - m4.w) / (dn4.w + 1e-16f);
    const long long OFF = 4800000LL;
    *(float4*)&out[OFF + e * 4] = a;
}

// ---------------- launch ----------------
extern "C" void kernel_launch(void* const* d_in, const int* in_sizes, int n_in,
                              void* d_out, int out_size) {
    const float* x         = (const float*)d_in[0];
    const int*   ei        = (const int*)d_in[1];
    const float* edge_attr = (const float*)d_in[2];
    const float* Wl        = (const float*)d_in[3];
    const float* bl        = (const float*)d_in[4];
    const float* Wr        = (const float*)d_in[5];
    const float* br        = (const float*)d_in[6];
    const float* We        = (const float*)d_in[7];
    const float* att       = (const float*)d_in[8];
    const float* bias_out  = (const float*)d_in[9];
    const float* Wres      = (const float*)d_in[10];
    const float* bres      = (const float*)d_in[11];
    float* out = (float*)d_out;

    k_convert<<<(NE + 255) / 256, 256>>>(ei);
    k_proj<<<(NN + 31) / 32, 192>>>(x, Wl, bl, Wr, br, Wres, bres);
    k_hist<<<(NE + 255) / 256, 256>>>();
    k_scan1<<<NBLK, 256>>>();
    k_scan2<<<1, 256>>>();
    k_scan3<<<NBLK, 256>>>();
    k_scatter<<<(NE + 255) / 256, 256>>>();
    k_node<<<(NN + 7) / 8, 256>>>(edge_attr, We, att, bias_out, out);

    if (out_size >= 4800000) k_ei<<<(NE + 255) / 256, 256>>>(out);
    if (out_size >= 8000000) k_alpha<<<(NE + 255) / 256, 256>>>(out);
}

// round 3
// speedup vs baseline: 2.3709x; 1.1187x over previous
#include <cuda_runtime.h>
#include <cuda_bf16.h>
#include <math.h>
#include <stdint.h>

#define NN 50000
#define NE 800000
#define HDIM 64
#define NBLK 196   // ceil(50000/256)

#define EI_OFF  3200000LL
#define AL_OFF  4800000LL

// ---------------- scratch (static device globals; no allocation) ----------------
// g_deg is zero at module load and re-zeroed by k_node at the end of every call,
// so every kernel_launch execution performs identical work (deterministic).
__device__ int   g_src[NE];
__device__ int   g_dst[NE];
__device__ int   g_deg[NN];
__device__ int   g_rowstart[NN + 1];
__device__ int   g_cursor[NN];
__device__ int   g_elist[NE];
__device__ int   g_part[256];
__device__ float g_xl[NN * HDIM];
__device__ float g_xr[NN * HDIM];
__device__ float g_res[NN * HDIM];
__device__ float g_score[NE * 4];   // only used for rare deg>128 fallback
__device__ float g_m[NN * 4];
__device__ float g_denom[NN * 4];

// ---------------- K0: convert (+int64 detect) + degree histogram + ei passthrough ----------------
__global__ void k_convert(const int* __restrict__ ei, float* __restrict__ out, int write_ei) {
    __shared__ int s64;
    if (threadIdx.x == 0) {
        int f = 1;
#pragma unroll
        for (int i = 0; i < 16; i++) f &= (ei[2 * i + 1] == 0);
        s64 = f;
    }
    __syncthreads();
    int is64 = s64;
    int e = blockIdx.x * blockDim.x + threadIdx.x;
    if (e < NE) {
        int s, d;
        if (is64) {
            s = ei[2 * e];
            d = ei[2 * (NE + e)];
        } else {
            s = ei[e];
            d = ei[NE + e];
        }
        g_src[e] = s;
        g_dst[e] = d;
        atomicAdd(&g_deg[d], 1);
        if (write_ei) {
            out[EI_OFF + e]      = (float)s;
            out[EI_OFF + NE + e] = (float)d;
        }
    }
}

// ---------------- K1: fused projections, register-blocked ----------------
__global__ void __launch_bounds__(192) k_proj(
    const float* __restrict__ x,
    const float* __restrict__ Wl, const float* __restrict__ bl,
    const float* __restrict__ Wr, const float* __restrict__ br,
    const float* __restrict__ Wres, const float* __restrict__ bres)
{
    __shared__ __align__(16) float sx[128 * 32];  // [k][r]
    int tid = threadIdx.x;
    int lane = tid & 31;
    int warp = tid >> 5;
    int row0 = blockIdx.x * 32;
    const float4* x4 = reinterpret_cast<const float4*>(x);
    for (int idx = tid; idx < 1024; idx += 192) {
        int r = idx & 31, c4 = idx >> 5;
        int row = row0 + r;
        float4 v = make_float4(0.f, 0.f, 0.f, 0.f);
        if (row < NN) v = x4[row * 32 + c4];
        int k = c4 * 4;
        sx[(k + 0) * 32 + r] = v.x;
        sx[(k + 1) * 32 + r] = v.y;
        sx[(k + 2) * 32 + r] = v.z;
        sx[(k + 3) * 32 + r] = v.w;
    }
    __syncthreads();

    int mat = warp % 3;
    int rh  = warp / 3;    // 0 or 1 -> rows [rh*16, rh*16+16)
    const float* W = (mat == 0) ? Wl : (mat == 1) ? Wr : Wres;
    const float* B = (mat == 0) ? bl : (mat == 1) ? br : bres;
    float* Out = (mat == 0) ? g_xl : (mat == 1) ? g_xr : g_res;
    int j0 = lane, j1 = lane + 32;

    unsigned long long acc0[8], acc1[8];
#pragma unroll
    for (int i = 0; i < 8; i++) { acc0[i] = 0ULL; acc1[i] = 0ULL; }

#pragma unroll 2
    for (int k = 0; k < 128; k++) {
        float w0 = W[k * 64 + j0];
        float w1 = W[k * 64 + j1];
        unsigned long long wd0, wd1;
        asm("mov.b64 %0, {%1, %2};" : "=l"(wd0) : "f"(w0), "f"(w0));
        asm("mov.b64 %0, {%1, %2};" : "=l"(wd1) : "f"(w1), "f"(w1));
        const unsigned long long* xp =
            reinterpret_cast<const unsigned long long*>(&sx[k * 32 + rh * 16]);
#pragma unroll
        for (int rp = 0; rp < 8; rp++) {
            unsigned long long xv = xp[rp];   // lane-uniform -> broadcast
            asm("fma.rn.f32x2 %0, %1, %2, %0;" : "+l"(acc0[rp]) : "l"(xv), "l"(wd0));
            asm("fma.rn.f32x2 %0, %1, %2, %0;" : "+l"(acc1[rp]) : "l"(xv), "l"(wd1));
        }
    }

    float b0 = B[j0], b1 = B[j1];
#pragma unroll
    for (int rp = 0; rp < 8; rp++) {
        int row = row0 + rh * 16 + 2 * rp;
        float lo0 = __uint_as_float((unsigned)(acc0[rp] & 0xffffffffULL)) + b0;
        float hi0 = __uint_as_float((unsigned)(acc0[rp] >> 32)) + b0;
        float lo1 = __uint_as_float((unsigned)(acc1[rp] & 0xffffffffULL)) + b1;
        float hi1 = __uint_as_float((unsigned)(acc1[rp] >> 32)) + b1;
        if (row < NN)     { Out[row * 64 + j0] = lo0; Out[row * 64 + j1] = lo1; }
        if (row + 1 < NN) { Out[(row + 1) * 64 + j0] = hi0; Out[(row + 1) * 64 + j1] = hi1; }
    }
}

// ---------------- K3a: per-block partial sums ----------------
__global__ void k_scan1() {
    __shared__ int s[256];
    int t = threadIdx.x;
    int idx = blockIdx.x * 256 + t;
    int v = (idx < NN) ? g_deg[idx] : 0;
    s[t] = v;
    __syncthreads();
#pragma unroll
    for (int off = 128; off > 0; off >>= 1) {
        if (t < off) s[t] += s[t + off];
        __syncthreads();
    }
    if (t == 0) g_part[blockIdx.x] = s[0];
}

// ---------------- K3b: scan of partials (1 block) ----------------
__global__ void k_scan2() {
    __shared__ int s[256];
    int t = threadIdx.x;
    int v = (t < NBLK) ? g_part[t] : 0;
    s[t] = v;
    __syncthreads();
#pragma unroll
    for (int off = 1; off < 256; off <<= 1) {
        int u = (t >= off) ? s[t - off] : 0;
        __syncthreads();
        s[t] += u;
        __syncthreads();
    }
    if (t < NBLK) g_part[t] = s[t] - v;   // exclusive block offset
    if (t == 255) g_rowstart[NN] = s[255];
}

// ---------------- K3c: local exclusive scan + block offset ----------------
__global__ void k_scan3() {
    __shared__ int s[256];
    int t = threadIdx.x;
    int idx = blockIdx.x * 256 + t;
    int v = (idx < NN) ? g_deg[idx] : 0;
    s[t] = v;
    __syncthreads();
#pragma unroll
    for (int off = 1; off < 256; off <<= 1) {
        int u = (t >= off) ? s[t - off] : 0;
        __syncthreads();
        s[t] += u;
        __syncthreads();
    }
    int excl = s[t] - v + g_part[blockIdx.x];
    if (idx < NN) {
        g_rowstart[idx] = excl;
        g_cursor[idx]   = excl;
    }
}

// ---------------- K4: scatter edges into CSR ----------------
__global__ void k_scatter() {
    int e = blockIdx.x * blockDim.x + threadIdx.x;
    if (e < NE) {
        int d = g_dst[e];
        int pos = atomicAdd(&g_cursor[d], 1);
        g_elist[pos] = e;
    }
}

// ---------------- K5: per-node fused score + softmax + aggregation + epilogue + alpha ----------------
// One warp per node. lane l owns output elements (2l, 2l+1); head = l>>3.
__global__ void __launch_bounds__(256) k_node(
    const float* __restrict__ edge_attr,
    const float* __restrict__ We,
    const float* __restrict__ att,
    const float* __restrict__ bias_out,
    float* __restrict__ out, int do_alpha)
{
    __shared__ int sbuf[8 * 128];
    __shared__ __align__(16) float ssc[8][128 * 4];  // per-edge per-head scores
    int warp = threadIdx.x >> 5;
    int lane = threadIdx.x & 31;
    int n = blockIdx.x * 8 + warp;
    if (n >= NN) return;
    int* buf = &sbuf[warp * 128];
    float* psc = ssc[warp];

    int start = g_rowstart[n];
    int deg = g_rowstart[n + 1] - start;

    // deterministic: sort this node's edge ids ascending
    if (deg <= 32) {
        int myid = (lane < deg) ? g_elist[start + lane] : 0x7fffffff;
        int rank = 0;
#pragma unroll
        for (int j = 0; j < 32; j++) {
            int o = __shfl_sync(0xffffffffu, myid, j);
            rank += (o < myid);
        }
        if (lane < deg) buf[rank] = myid;
    } else {
        int dd = min(deg, 128);
        for (int i = lane; i < dd; i += 32) {
            int v = g_elist[start + i];
            int rank = 0;
            for (int j = 0; j < dd; j++) rank += (g_elist[start + j] < v);
            buf[rank] = v;
        }
    }
    __syncwarp();
    bool use_buf = (deg <= 128);

    float2 xr2 = *(const float2*)&g_xr[n * 64 + 2 * lane];
    float2 We2 = *(const float2*)&We[2 * lane];
    float2 at2 = *(const float2*)&att[2 * lane];

    float m = __int_as_float(0xff800000);  // -inf
    float denom = 0.f;
    float accx = 0.f, accy = 0.f;

    // depth-1 pipeline on both edge meta and the xl gather
    int e_n = 0; float ea_n = 0.f; float2 xl_n = make_float2(0.f, 0.f);
    if (deg > 0) {
        e_n = use_buf ? buf[0] : g_elist[start];
        int s0 = g_src[e_n];
        ea_n = edge_attr[e_n];
        xl_n = *(const float2*)&g_xl[s0 * 64 + 2 * lane];
    }
    for (int i = 0; i < deg; i++) {
        int ecur = e_n;
        float eacur = ea_n;
        float2 xl2 = xl_n;
        if (i + 1 < deg) {   // prefetch next edge (meta + feature)
            e_n = use_buf ? buf[i + 1] : g_elist[start + i + 1];
            int sn = g_src[e_n];
            ea_n = edge_attr[e_n];
            xl_n = *(const float2*)&g_xl[sn * 64 + 2 * lane];
        }
        float fx = xl2.x + xr2.x + eacur * We2.x;
        float fy = xl2.y + xr2.y + eacur * We2.y;
        fx = fx >= 0.f ? fx : 0.2f * fx;
        fy = fy >= 0.f ? fy : 0.2f * fy;
        float p = fx * at2.x + fy * at2.y;
        p += __shfl_xor_sync(0xffffffffu, p, 1);
        p += __shfl_xor_sync(0xffffffffu, p, 2);
        p += __shfl_xor_sync(0xffffffffu, p, 4);
        if ((lane & 7) == 0) {
            if (use_buf) psc[i * 4 + (lane >> 3)] = p;
            else         g_score[ecur * 4 + (lane >> 3)] = p;
        }
        float mnew = fmaxf(m, p);
        float scale = __expf(m - mnew);
        float ex = __expf(p - mnew);
        denom = denom * scale + ex;
        accx = accx * scale + ex * xl2.x;
        accy = accy * scale + ex * xl2.y;
        m = mnew;
    }

    float dfin = denom + 1e-16f;
    float2 r2  = *(const float2*)&g_res[n * 64 + 2 * lane];
    float2 bo2 = *(const float2*)&bias_out[2 * lane];
    float ox = accx / dfin + bo2.x + r2.x;
    float oy = accy / dfin + bo2.y + r2.y;
    ox = ox > 0.f ? ox : expm1f(ox);
    oy = oy > 0.f ? oy : expm1f(oy);
    *(float2*)&out[n * 64 + 2 * lane] = make_float2(ox, oy);

    // reset degree counter for the next call (keeps every call identical work)
    if (lane == 0) g_deg[n] = 0;

    if (do_alpha) {
        // per-head m/denom are identical across each 8-lane group; broadcast all 4
        float m0 = __shfl_sync(0xffffffffu, m, 0);
        float m1 = __shfl_sync(0xffffffffu, m, 8);
        float m2 = __shfl_sync(0xffffffffu, m, 16);
        float m3 = __shfl_sync(0xffffffffu, m, 24);
        float d0 = __shfl_sync(0xffffffffu, denom, 0)  + 1e-16f;
        float d1 = __shfl_sync(0xffffffffu, denom, 8)  + 1e-16f;
        float d2 = __shfl_sync(0xffffffffu, denom, 16) + 1e-16f;
        float d3 = __shfl_sync(0xffffffffu, denom, 24) + 1e-16f;
        __syncwarp();
        for (int i = lane; i < deg; i += 32) {
            int e = use_buf ? buf[i] : g_elist[start + i];
            float4 s4 = use_buf ? *(const float4*)&psc[i * 4]
                                : *(const float4*)&g_score[e * 4];
            float4 a;
            a.x = __expf(s4.x - m0) / d0;
            a.y = __expf(s4.y - m1) / d1;
            a.z = __expf(s4.z - m2) / d2;
            a.w = __expf(s4.w - m3) / d3;
            *(float4*)&out[AL_OFF + (long long)e * 4] = a;
        }
    }
}

// ---------------- launch ----------------
extern "C" void kernel_launch(void* const* d_in, const int* in_sizes, int n_in,
                              void* d_out, int out_size) {
    const float* x         = (const float*)d_in[0];
    const int*   ei        = (const int*)d_in[1];
    const float* edge_attr = (const float*)d_in[2];
    const float* Wl        = (const float*)d_in[3];
    const float* bl        = (const float*)d_in[4];
    const float* Wr        = (const float*)d_in[5];
    const float* br        = (const float*)d_in[6];
    const float* We        = (const float*)d_in[7];
    const float* att       = (const float*)d_in[8];
    const float* bias_out  = (const float*)d_in[9];
    const float* Wres      = (const float*)d_in[10];
    const float* bres      = (const float*)d_in[11];
    float* out = (float*)d_out;

    int write_ei = (out_size >= 4800000);
    int do_alpha = (out_size >= 8000000);

    // side stream for the independent projection GEMM (created once, outside capture)
    static cudaStream_t s2 = 0;
    static cudaEvent_t evA = 0, evB = 0;
    if (!s2) {
        cudaStreamCreateWithFlags(&s2, cudaStreamNonBlocking);
        cudaEventCreateWithFlags(&evA, cudaEventDisableTiming);
        cudaEventCreateWithFlags(&evB, cudaEventDisableTiming);
    }

    // fork: proj runs concurrently with the CSR-build chain
    cudaEventRecord(evA, 0);
    cudaStreamWaitEvent(s2, evA, 0);
    k_proj<<<(NN + 31) / 32, 192, 0, s2>>>(x, Wl, bl, Wr, br, Wres, bres);
    cudaEventRecord(evB, s2);

    k_convert<<<(NE + 255) / 256, 256>>>(ei, out, write_ei);
    k_scan1<<<NBLK, 256>>>();
    k_scan2<<<1, 256>>>();
    k_scan3<<<NBLK, 256>>>();
    k_scatter<<<(NE + 255) / 256, 256>>>();

    // join: node pass needs both the CSR and the projections
    cudaStreamWaitEvent(0, evB, 0);
    k_node<<<(NN + 7) / 8, 256>>>(edge_attr, We, att, bias_out, out, do_alpha);
}